// round 16
// baseline (speedup 1.0000x reference)
#include <cuda_runtime.h>
#include <math.h>

#define NPOP   44
#define BATCH  400000
#define B4     (BATCH / 4)
#define BPP    13
#define CHUNK4 ((B4 + BPP - 1) / BPP)   // 7693
#define TPB    512

#define MAXB   232
#define G      2048
#define XLO    (-6.5f)
#define XHI    (6.5f)

// magic-floor constants for slot = floor((x - XLO) * G/(XHI-XLO))
#define INVW   157.53846153846155f     // G / 13
#define CHALF  1023.5f                 // -XLO*INVW - 0.5
#define MAGIC  8388608.0f              // 2^23
#define XCLO   (-6.4968f)
#define XCHI   (6.4968f)
#define SLOTMASK 0x7FF

#define MULTI_FLAG 0x8000

// --------- scratch (device globals; no allocs) ---------
__device__ float  g_brk[NPOP][MAXB];
__device__ int    g_nb[NPOP];
__device__ float2 g_pieces[NPOP][MAXB];
__device__ float2 g_grid[NPOP][G];

struct Wt {
    float w1[4], b1[4];
    float w2[8][4], b2[8];
    float w3[4][8], b3[4];
    float w4[4], b4;
};

__device__ __forceinline__ int lbound(const float* a, int n, float x) {
    int lo = 0, hi = n;
    while (lo < hi) { int m = (lo + hi) >> 1; if (a[m] < x) lo = m + 1; else hi = m; }
    return lo;
}

__device__ __forceinline__ float seg_mid(const float* brk, int nb, int s) {
    if (nb == 0) return 0.f;
    if (s == 0)  return brk[0] - 1.f;
    if (s == nb) return brk[nb - 1] + 1.f;
    return 0.5f * (brk[s - 1] + brk[s]);
}

__device__ __forceinline__ void sort_smem(float* a, float* t, int n, int tid) {
    float v = 0.f; int r = 0;
    if (tid < n) {
        v = a[tid];
        for (int k = 0; k < n; k++) {
            float u = a[k];
            r += (u < v) || (u == v && k < tid);
        }
    }
    __syncthreads();
    if (tid < n) t[r] = v;
    __syncthreads();
    if (tid < n) a[tid] = t[tid];
    __syncthreads();
}

// ---------------- precompute: PWL collapse + grid fill (44 blocks) ----------------
__global__ void __launch_bounds__(256) precompute_kernel(
    const float* __restrict__ L1, const float* __restrict__ L2,
    const float* __restrict__ L3, const float* __restrict__ L4,
    const float* __restrict__ B1, const float* __restrict__ B2,
    const float* __restrict__ B3, const float* __restrict__ B4v)
{
    __shared__ Wt w;
    __shared__ float  brk[MAXB];
    __shared__ float  tmp[MAXB];
    __shared__ float2 pieces_s[MAXB];
    __shared__ int nb_sh, cnt;

    const int pop = blockIdx.x;
    const int tid = threadIdx.x;

    if (tid < 4)  { w.w1[tid] = L1[pop*4+tid]; w.b1[tid] = B1[pop*4+tid];
                    w.w4[tid] = L4[pop*4+tid]; w.b3[tid] = B3[pop*4+tid]; }
    if (tid < 32) { ((float*)w.w2)[tid] = L2[pop*32+tid];
                    ((float*)w.w3)[tid] = L3[pop*32+tid]; }
    if (tid < 8)  w.b2[tid] = B2[pop*8+tid];
    if (tid == 0) { w.b4 = B4v[pop]; nb_sh = 0; cnt = 0; }
    __syncthreads();

    // ---- stage A: layer-1 breakpoints (<=4) ----
    if (tid == 0) {
        float c[4]; int n = 0;
        for (int i = 0; i < 4; i++)
            if (w.w1[i] != 0.0f) { float x0 = -w.b1[i] / w.w1[i]; if (isfinite(x0)) c[n++] = x0; }
        for (int i = 1; i < n; i++) { float v = c[i]; int j = i-1;
            while (j >= 0 && c[j] > v) { c[j+1] = c[j]; j--; } c[j+1] = v; }
        for (int i = 0; i < n; i++) brk[i] = c[i];
        nb_sh = n;
    }
    __syncthreads();
    int nb = nb_sh;

    // ---- stage B: layer-2 preact crossings ----
    {
        int tasks = (nb + 1) * 8;
        if (tid < tasks) {
            int seg = tid >> 3, j = tid & 7;
            float xm = seg_mid(brk, nb, seg);
            float s = 0.f, v = w.b2[j];
            for (int k = 0; k < 4; k++) {
                float p = fmaf(w.w1[k], xm, w.b1[k]);
                if (p > 0.f) { s += w.w2[j][k] * w.w1[k]; v += w.w2[j][k] * p; }
            }
            if (s != 0.f) {
                float x0 = xm - v / s;
                float lo = (seg == 0)  ? -3.4e38f : brk[seg-1];
                float hi = (seg == nb) ?  3.4e38f : brk[seg];
                if (isfinite(x0) && x0 > lo && x0 < hi) {
                    int i = atomicAdd(&cnt, 1);
                    tmp[i] = x0;
                }
            }
        }
        __syncthreads();
        if (tid < cnt) brk[nb + tid] = tmp[tid];
        __syncthreads();
        if (tid == 0) { nb_sh += cnt; cnt = 0; }
        __syncthreads();
        nb = nb_sh;
        sort_smem(brk, tmp, nb, tid);
    }

    // ---- stage C: layer-3 preact crossings ----
    {
        int tasks = (nb + 1) * 4;
        if (tid < tasks) {
            int seg = tid >> 2, i = tid & 3;
            float xm = seg_mid(brk, nb, seg);
            float hs[4], hv[4];
            for (int k = 0; k < 4; k++) {
                float p = fmaf(w.w1[k], xm, w.b1[k]);
                bool m = p > 0.f;
                hs[k] = m ? w.w1[k] : 0.f;
                hv[k] = m ? p : 0.f;
            }
            float s = 0.f, v = w.b3[i];
            for (int j = 0; j < 8; j++) {
                float us = 0.f, uv = w.b2[j];
                for (int k = 0; k < 4; k++) { us += w.w2[j][k]*hs[k]; uv += w.w2[j][k]*hv[k]; }
                if (uv > 0.f) { s += w.w3[i][j]*us; v += w.w3[i][j]*uv; }
            }
            if (s != 0.f) {
                float x0 = xm - v / s;
                float lo = (seg == 0)  ? -3.4e38f : brk[seg-1];
                float hi = (seg == nb) ?  3.4e38f : brk[seg];
                if (isfinite(x0) && x0 > lo && x0 < hi) {
                    int i2 = atomicAdd(&cnt, 1);
                    tmp[i2] = x0;
                }
            }
        }
        __syncthreads();
        if (tid < cnt) brk[nb + tid] = tmp[tid];
        __syncthreads();
        if (tid == 0) { nb_sh += cnt; cnt = 0; }
        __syncthreads();
        nb = nb_sh;
        sort_smem(brk, tmp, nb, tid);
    }

    // ---- per-segment affine pieces ----
    if (tid <= nb) {
        int seg = tid;
        float xm = seg_mid(brk, nb, seg);
        float hs[4], hv[4];
        for (int k = 0; k < 4; k++) {
            float p = fmaf(w.w1[k], xm, w.b1[k]);
            bool m = p > 0.f;
            hs[k] = m ? w.w1[k] : 0.f;
            hv[k] = m ? p : 0.f;
        }
        float gs[8], gv[8];
        for (int j = 0; j < 8; j++) {
            float us = 0.f, uv = w.b2[j];
            for (int k = 0; k < 4; k++) { us += w.w2[j][k]*hs[k]; uv += w.w2[j][k]*hv[k]; }
            bool m = uv > 0.f;
            gs[j] = m ? us : 0.f;
            gv[j] = m ? uv : 0.f;
        }
        float rs[4], rv[4];
        for (int i = 0; i < 4; i++) {
            float vs = 0.f, vv = w.b3[i];
            for (int j = 0; j < 8; j++) { vs += w.w3[i][j]*gs[j]; vv += w.w3[i][j]*gv[j]; }
            bool m = vv > 0.f;
            rs[i] = m ? vs : 0.f;
            rv[i] = m ? vv : 0.f;
        }
        float os = 0.f, ov = w.b4;
        for (int i = 0; i < 4; i++) { os += w.w4[i]*rs[i]; ov += w.w4[i]*rv[i]; }
        float2 pc = make_float2(os, ov - os * xm);
        pieces_s[seg] = pc;
        g_pieces[pop][seg] = pc;
    }
    if (tid < nb) g_brk[pop][tid] = brk[tid];
    if (tid == 0) g_nb[pop] = nb;
    __syncthreads();

    // ---- grid fill ----
    // pure slot:          (slope, intercept)
    // 1-break slot:       (NaN | piece_idx,              brk)
    // multi-break slot:   (NaN | MULTI_FLAG | piece_idx, brk0)
    {
        const float wslot = (XHI - XLO) / (float)G;
        for (int s = tid; s < G; s += blockDim.x) {
            float slo = (s == 0)     ? -3.4e38f : XLO + s * wslot;
            float shi = (s == G - 1) ?  3.4e38f : XLO + (s + 1) * wslot;
            int plo = lbound(brk, nb, slo);
            int phi = lbound(brk, nb, shi);
            float2 e;
            if (plo == phi) {
                e = pieces_s[plo];
            } else if (phi == plo + 1) {
                e = make_float2(__int_as_float(0x7FC00000 | plo), brk[plo]);
            } else {
                e = make_float2(__int_as_float(0x7FC00000 | MULTI_FLAG | plo), brk[plo]);
            }
            g_grid[pop][s] = e;
        }
    }

    // PDL: allow the dependent eval kernel to launch
    asm volatile("griddepcontrol.launch_dependents;");
}

// ---------------- eval: unroll x2 + cross-iteration pipelining ----------------
__device__ __forceinline__ int slot_of(float x) {
    float xc = fminf(fmaxf(x, XCLO), XCHI);
    float t  = fmaf(xc, INVW, CHALF);
    float f  = t + MAGIC;
    return __float_as_int(f) & SLOTMASK;
}

// exact fixup reusing the register-resident table entry c (no re-lookup)
__device__ __forceinline__ float fixc(float x, float o, float2 c,
                                      const float2* __restrict__ pieces,
                                      const float* __restrict__ brk, int nb)
{
    bool bad = !(o == o);
    int pl = __float_as_int(c.x);
    int p = (pl & 0x3FF) + ((x >= c.y) ? 1 : 0);
    if (bad && (pl & MULTI_FLAG)) {          // ultra-rare: >=2 breaks in slot
        p = pl & 0x3FF;
        while (p < nb && x >= brk[p]) p++;
    }
    p = min(p, nb);                          // in-bounds even when !bad
    float2 pc = pieces[p];
    return bad ? fmaf(pc.x, x, pc.y) : o;
}

__device__ __forceinline__ float4 body4(float4 x,
                                        const float2* __restrict__ tab,
                                        const float2* __restrict__ pieces,
                                        const float*  __restrict__ brk, int nb)
{
    float2 c0 = tab[slot_of(x.x)];
    float2 c1 = tab[slot_of(x.y)];
    float2 c2 = tab[slot_of(x.z)];
    float2 c3 = tab[slot_of(x.w)];
    float4 o;
    o.x = fmaf(c0.x, x.x, c0.y);
    o.y = fmaf(c1.x, x.y, c1.y);
    o.z = fmaf(c2.x, x.z, c2.y);
    o.w = fmaf(c3.x, x.w, c3.y);
    float chk = (o.x + o.y) + (o.z + o.w);
    if (!(chk == chk)) {
        o.x = fixc(x.x, o.x, c0, pieces, brk, nb);
        o.y = fixc(x.y, o.y, c1, pieces, brk, nb);
        o.z = fixc(x.z, o.z, c2, pieces, brk, nb);
        o.w = fixc(x.w, o.w, c3, pieces, brk, nb);
    }
    return o;
}

__global__ void __launch_bounds__(TPB, 3) eval_kernel(const float* __restrict__ X,
                                                      float* __restrict__ out)
{
    __shared__ float2 tab_s[G];
    __shared__ float2 pieces_s[MAXB];
    __shared__ float  brk_s[MAXB];
    __shared__ int    nb_s;

    const int pop = blockIdx.y;
    const int blk = blockIdx.x;

    const int base = blk * CHUNK4;
    const int cnt  = min(CHUNK4, B4 - base);

    const float4* __restrict__ X4 =
        reinterpret_cast<const float4*>(X) + (size_t)pop * B4 + base;
    float4* __restrict__ O4 =
        reinterpret_cast<float4*>(out) + (size_t)pop * B4 + base;

    // prefetch the first pair of X BEFORE the PDL wait — X doesn't depend
    // on precompute, so this overlaps the precompute tail + hides DRAM latency
    int t = threadIdx.x;
    bool has  = t < cnt;
    bool has2 = t + TPB < cnt;
    float4 xa, xb;
    if (has)  xa = __ldcs(X4 + t);
    if (has2) xb = __ldcs(X4 + t + TPB);

    // PDL: wait until precompute's writes are visible
    asm volatile("griddepcontrol.wait;");

    for (int i = threadIdx.x; i < G; i += TPB) tab_s[i] = g_grid[pop][i];
    for (int i = threadIdx.x; i < MAXB; i += TPB) {
        pieces_s[i] = g_pieces[pop][i];
        brk_s[i]    = g_brk[pop][i];
    }
    if (threadIdx.x == 0) nb_s = g_nb[pop];
    __syncthreads();
    const int nb = nb_s;

    // software-pipelined main loop: prefetch next pair, evaluate current pair
    while (has2) {
        int tn = t + 2 * TPB;
        bool nhas  = tn < cnt;
        bool nhas2 = tn + TPB < cnt;
        float4 na, nbv;
        if (nhas)  na  = __ldcs(X4 + tn);
        if (nhas2) nbv = __ldcs(X4 + tn + TPB);

        float4 oa = body4(xa, tab_s, pieces_s, brk_s, nb);
        float4 ob = body4(xb, tab_s, pieces_s, brk_s, nb);
        __stcs(O4 + t,       oa);
        __stcs(O4 + t + TPB, ob);

        t = tn; xa = na; xb = nbv; has = nhas; has2 = nhas2;
    }
    if (has) {
        float4 o = body4(xa, tab_s, pieces_s, brk_s, nb);
        __stcs(O4 + t, o);
    }
}

extern "C" void kernel_launch(void* const* d_in, const int* in_sizes, int n_in,
                              void* d_out, int out_size)
{
    const float* X  = (const float*)d_in[0];
    const float* L1 = (const float*)d_in[1];
    const float* L2 = (const float*)d_in[2];
    const float* L3 = (const float*)d_in[3];
    const float* L4 = (const float*)d_in[4];
    const float* B1 = (const float*)d_in[5];
    const float* B2 = (const float*)d_in[6];
    const float* B3 = (const float*)d_in[7];
    const float* B4v = (const float*)d_in[8];
    float* out = (float*)d_out;

    precompute_kernel<<<NPOP, 256>>>(L1, L2, L3, L4, B1, B2, B3, B4v);

    cudaLaunchConfig_t cfg = {};
    cfg.gridDim  = dim3(BPP, NPOP);
    cfg.blockDim = dim3(TPB);
    cfg.dynamicSmemBytes = 0;
    cfg.stream = 0;
    cudaLaunchAttribute attrs[1];
    attrs[0].id = cudaLaunchAttributeProgrammaticStreamSerialization;
    attrs[0].val.programmaticStreamSerializationAllowed = 1;
    cfg.attrs = attrs;
    cfg.numAttrs = 1;
    cudaLaunchKernelEx(&cfg, eval_kernel, X, out);
}

// round 17
// speedup vs baseline: 1.2541x; 1.2541x over previous
#include <cuda_runtime.h>
#include <math.h>

#define NPOP   44
#define BATCH  400000
#define B4     (BATCH / 4)
#define BPP    13
#define CHUNK4 ((B4 + BPP - 1) / BPP)   // 7693
#define TPB    512

#define MAXB   232
#define G      2048
#define NSLICE 8
#define XLO    (-6.5f)
#define XHI    (6.5f)

// magic-floor constants for slot = floor((x - XLO) * G/(XHI-XLO))
#define INVW   157.53846153846155f     // G / 13
#define CHALF  1023.5f                 // -XLO*INVW - 0.5
#define MAGIC  8388608.0f              // 2^23
#define XCLO   (-6.4968f)
#define XCHI   (6.4968f)
#define SLOTMASK 0x7FF

#define MULTI_FLAG 0x8000

// --------- scratch (device globals; no allocs) ---------
__device__ float  g_brk[NPOP][MAXB];
__device__ int    g_nb[NPOP];
__device__ float2 g_pieces[NPOP][MAXB];
__device__ float2 g_grid[NPOP][G];

struct Wt {
    float w1[4], b1[4];
    float w2[8][4], b2[8];
    float w3[4][8], b3[4];
    float w4[4], b4;
};

__device__ __forceinline__ int lbound(const float* a, int n, float x) {
    int lo = 0, hi = n;
    while (lo < hi) { int m = (lo + hi) >> 1; if (a[m] < x) lo = m + 1; else hi = m; }
    return lo;
}

__device__ __forceinline__ float seg_mid(const float* brk, int nb, int s) {
    if (nb == 0) return 0.f;
    if (s == 0)  return brk[0] - 1.f;
    if (s == nb) return brk[nb - 1] + 1.f;
    return 0.5f * (brk[s - 1] + brk[s]);
}

__device__ __forceinline__ void sort_smem(float* a, float* t, int n, int tid) {
    float v = 0.f; int r = 0;
    if (tid < n) {
        v = a[tid];
        for (int k = 0; k < n; k++) {
            float u = a[k];
            r += (u < v) || (u == v && k < tid);
        }
    }
    __syncthreads();
    if (tid < n) t[r] = v;
    __syncthreads();
    if (tid < n) a[tid] = t[tid];
    __syncthreads();
}

// ---------------- precompute: PWL collapse, sliced grid fill ----------------
__global__ void __launch_bounds__(256) precompute_kernel(
    const float* __restrict__ L1, const float* __restrict__ L2,
    const float* __restrict__ L3, const float* __restrict__ L4,
    const float* __restrict__ B1, const float* __restrict__ B2,
    const float* __restrict__ B3, const float* __restrict__ B4v)
{
    __shared__ Wt w;
    __shared__ float  brk[MAXB];
    __shared__ float  tmp[MAXB];
    __shared__ float2 pieces_s[MAXB];
    __shared__ int nb_sh, cnt;

    const int pop   = blockIdx.x;
    const int slice = blockIdx.y;
    const int tid   = threadIdx.x;

    if (tid < 4)  { w.w1[tid] = L1[pop*4+tid]; w.b1[tid] = B1[pop*4+tid];
                    w.w4[tid] = L4[pop*4+tid]; w.b3[tid] = B3[pop*4+tid]; }
    if (tid < 32) { ((float*)w.w2)[tid] = L2[pop*32+tid];
                    ((float*)w.w3)[tid] = L3[pop*32+tid]; }
    if (tid < 8)  w.b2[tid] = B2[pop*8+tid];
    if (tid == 0) { w.b4 = B4v[pop]; nb_sh = 0; cnt = 0; }
    __syncthreads();

    // ---- stage A: layer-1 breakpoints (<=4) ----
    if (tid == 0) {
        float c[4]; int n = 0;
        for (int i = 0; i < 4; i++)
            if (w.w1[i] != 0.0f) { float x0 = -w.b1[i] / w.w1[i]; if (isfinite(x0)) c[n++] = x0; }
        for (int i = 1; i < n; i++) { float v = c[i]; int j = i-1;
            while (j >= 0 && c[j] > v) { c[j+1] = c[j]; j--; } c[j+1] = v; }
        for (int i = 0; i < n; i++) brk[i] = c[i];
        nb_sh = n;
    }
    __syncthreads();
    int nb = nb_sh;

    // ---- stage B: layer-2 preact crossings ----
    {
        int tasks = (nb + 1) * 8;
        if (tid < tasks) {
            int seg = tid >> 3, j = tid & 7;
            float xm = seg_mid(brk, nb, seg);
            float s = 0.f, v = w.b2[j];
            for (int k = 0; k < 4; k++) {
                float p = fmaf(w.w1[k], xm, w.b1[k]);
                if (p > 0.f) { s += w.w2[j][k] * w.w1[k]; v += w.w2[j][k] * p; }
            }
            if (s != 0.f) {
                float x0 = xm - v / s;
                float lo = (seg == 0)  ? -3.4e38f : brk[seg-1];
                float hi = (seg == nb) ?  3.4e38f : brk[seg];
                if (isfinite(x0) && x0 > lo && x0 < hi) {
                    int i = atomicAdd(&cnt, 1);
                    tmp[i] = x0;
                }
            }
        }
        __syncthreads();
        if (tid < cnt) brk[nb + tid] = tmp[tid];
        __syncthreads();
        if (tid == 0) { nb_sh += cnt; cnt = 0; }
        __syncthreads();
        nb = nb_sh;
        sort_smem(brk, tmp, nb, tid);
    }

    // ---- stage C: layer-3 preact crossings ----
    {
        int tasks = (nb + 1) * 4;
        if (tid < tasks) {
            int seg = tid >> 2, i = tid & 3;
            float xm = seg_mid(brk, nb, seg);
            float hs[4], hv[4];
            for (int k = 0; k < 4; k++) {
                float p = fmaf(w.w1[k], xm, w.b1[k]);
                bool m = p > 0.f;
                hs[k] = m ? w.w1[k] : 0.f;
                hv[k] = m ? p : 0.f;
            }
            float s = 0.f, v = w.b3[i];
            for (int j = 0; j < 8; j++) {
                float us = 0.f, uv = w.b2[j];
                for (int k = 0; k < 4; k++) { us += w.w2[j][k]*hs[k]; uv += w.w2[j][k]*hv[k]; }
                if (uv > 0.f) { s += w.w3[i][j]*us; v += w.w3[i][j]*uv; }
            }
            if (s != 0.f) {
                float x0 = xm - v / s;
                float lo = (seg == 0)  ? -3.4e38f : brk[seg-1];
                float hi = (seg == nb) ?  3.4e38f : brk[seg];
                if (isfinite(x0) && x0 > lo && x0 < hi) {
                    int i2 = atomicAdd(&cnt, 1);
                    tmp[i2] = x0;
                }
            }
        }
        __syncthreads();
        if (tid < cnt) brk[nb + tid] = tmp[tid];
        __syncthreads();
        if (tid == 0) { nb_sh += cnt; cnt = 0; }
        __syncthreads();
        nb = nb_sh;
        sort_smem(brk, tmp, nb, tid);
    }

    // ---- per-segment affine pieces ----
    if (tid <= nb) {
        int seg = tid;
        float xm = seg_mid(brk, nb, seg);
        float hs[4], hv[4];
        for (int k = 0; k < 4; k++) {
            float p = fmaf(w.w1[k], xm, w.b1[k]);
            bool m = p > 0.f;
            hs[k] = m ? w.w1[k] : 0.f;
            hv[k] = m ? p : 0.f;
        }
        float gs[8], gv[8];
        for (int j = 0; j < 8; j++) {
            float us = 0.f, uv = w.b2[j];
            for (int k = 0; k < 4; k++) { us += w.w2[j][k]*hs[k]; uv += w.w2[j][k]*hv[k]; }
            bool m = uv > 0.f;
            gs[j] = m ? us : 0.f;
            gv[j] = m ? uv : 0.f;
        }
        float rs[4], rv[4];
        for (int i = 0; i < 4; i++) {
            float vs = 0.f, vv = w.b3[i];
            for (int j = 0; j < 8; j++) { vs += w.w3[i][j]*gs[j]; vv += w.w3[i][j]*gv[j]; }
            bool m = vv > 0.f;
            rs[i] = m ? vs : 0.f;
            rv[i] = m ? vv : 0.f;
        }
        float os = 0.f, ov = w.b4;
        for (int i = 0; i < 4; i++) { os += w.w4[i]*rs[i]; ov += w.w4[i]*rv[i]; }
        float2 pc = make_float2(os, ov - os * xm);
        pieces_s[seg] = pc;
        if (slice == 0) g_pieces[pop][seg] = pc;
    }
    if (slice == 0) {
        if (tid < nb) g_brk[pop][tid] = brk[tid];
        if (tid == 0) g_nb[pop] = nb;
    }
    __syncthreads();

    // ---- grid fill (slice) ----
    {
        const float wslot = (XHI - XLO) / (float)G;
        const int s0 = slice * (G / NSLICE);
        const int s1 = s0 + (G / NSLICE);
        for (int s = s0 + tid; s < s1; s += blockDim.x) {
            float slo = (s == 0)     ? -3.4e38f : XLO + s * wslot;
            float shi = (s == G - 1) ?  3.4e38f : XLO + (s + 1) * wslot;
            int plo = lbound(brk, nb, slo);
            int phi = lbound(brk, nb, shi);
            float2 e;
            if (plo == phi) {
                e = pieces_s[plo];
            } else if (phi == plo + 1) {
                e = make_float2(__int_as_float(0x7FC00000 | plo), brk[plo]);
            } else {
                e = make_float2(__int_as_float(0x7FC00000 | MULTI_FLAG | plo), brk[plo]);
            }
            g_grid[pop][s] = e;
        }
    }

    // PDL: allow the dependent eval kernel to launch
    asm volatile("griddepcontrol.launch_dependents;");
}

// ---------------- eval: R14 body (exact 32-reg / 4-CTA sweet spot) ----------------
__device__ __forceinline__ int slot_of(float x) {
    float xc = fminf(fmaxf(x, XCLO), XCHI);
    float t  = fmaf(xc, INVW, CHALF);
    float f  = t + MAGIC;
    return __float_as_int(f) & SLOTMASK;
}

// exact fixup reusing the register-resident table entry c (no re-lookup)
__device__ __forceinline__ float fixc(float x, float o, float2 c,
                                      const float2* __restrict__ pieces,
                                      const float* __restrict__ brk, int nb)
{
    bool bad = !(o == o);
    int pl = __float_as_int(c.x);
    int p = (pl & 0x3FF) + ((x >= c.y) ? 1 : 0);
    if (bad && (pl & MULTI_FLAG)) {          // ultra-rare: >=2 breaks in slot
        p = pl & 0x3FF;
        while (p < nb && x >= brk[p]) p++;
    }
    p = min(p, nb);                          // in-bounds even when !bad
    float2 pc = pieces[p];
    return bad ? fmaf(pc.x, x, pc.y) : o;
}

__device__ __forceinline__ float4 body4(float4 x,
                                        const float2* __restrict__ tab,
                                        const float2* __restrict__ pieces,
                                        const float*  __restrict__ brk, int nb)
{
    float2 c0 = tab[slot_of(x.x)];
    float2 c1 = tab[slot_of(x.y)];
    float2 c2 = tab[slot_of(x.z)];
    float2 c3 = tab[slot_of(x.w)];
    float4 o;
    o.x = fmaf(c0.x, x.x, c0.y);
    o.y = fmaf(c1.x, x.y, c1.y);
    o.z = fmaf(c2.x, x.z, c2.y);
    o.w = fmaf(c3.x, x.w, c3.y);
    float chk = (o.x + o.y) + (o.z + o.w);
    if (!(chk == chk)) {
        o.x = fixc(x.x, o.x, c0, pieces, brk, nb);
        o.y = fixc(x.y, o.y, c1, pieces, brk, nb);
        o.z = fixc(x.z, o.z, c2, pieces, brk, nb);
        o.w = fixc(x.w, o.w, c3, pieces, brk, nb);
    }
    return o;
}

__global__ void __launch_bounds__(TPB, 3) eval_kernel(const float* __restrict__ X,
                                                      float* __restrict__ out)
{
    __shared__ float2 tab_s[G];
    __shared__ float2 pieces_s[MAXB];
    __shared__ float  brk_s[MAXB];
    __shared__ int    nb_s;

    // PDL: wait until precompute's writes are visible
    asm volatile("griddepcontrol.wait;");

    const int pop = blockIdx.y;
    const int blk = blockIdx.x;

    // small copies first (their latency overlaps the wide table copy below)
    for (int i = threadIdx.x; i < MAXB; i += TPB) {
        pieces_s[i] = g_pieces[pop][i];
        brk_s[i]    = g_brk[pop][i];
    }
    if (threadIdx.x == 0) nb_s = g_nb[pop];
    // table copy as float4 (half the LDG/STS count of the float2 loop)
    {
        const float4* __restrict__ src = reinterpret_cast<const float4*>(g_grid[pop]);
        float4* dst = reinterpret_cast<float4*>(tab_s);
        for (int i = threadIdx.x; i < G / 2; i += TPB) dst[i] = src[i];
    }
    __syncthreads();
    const int nb = nb_s;

    const int base = blk * CHUNK4;
    const int cnt  = min(CHUNK4, B4 - base);

    const float4* __restrict__ X4 =
        reinterpret_cast<const float4*>(X) + (size_t)pop * B4 + base;
    float4* __restrict__ O4 =
        reinterpret_cast<float4*>(out) + (size_t)pop * B4 + base;

    int t = threadIdx.x;
    // unroll x2: two independent LDG+LDS chains in flight per thread
    for (; t + TPB < cnt; t += 2 * TPB) {
        float4 xa = __ldcs(X4 + t);
        float4 xb = __ldcs(X4 + t + TPB);
        float4 oa = body4(xa, tab_s, pieces_s, brk_s, nb);
        float4 ob = body4(xb, tab_s, pieces_s, brk_s, nb);
        __stcs(O4 + t, oa);
        __stcs(O4 + t + TPB, ob);
    }
    if (t < cnt) {
        float4 x = __ldcs(X4 + t);
        float4 o = body4(x, tab_s, pieces_s, brk_s, nb);
        __stcs(O4 + t, o);
    }
}

extern "C" void kernel_launch(void* const* d_in, const int* in_sizes, int n_in,
                              void* d_out, int out_size)
{
    const float* X  = (const float*)d_in[0];
    const float* L1 = (const float*)d_in[1];
    const float* L2 = (const float*)d_in[2];
    const float* L3 = (const float*)d_in[3];
    const float* L4 = (const float*)d_in[4];
    const float* B1 = (const float*)d_in[5];
    const float* B2 = (const float*)d_in[6];
    const float* B3 = (const float*)d_in[7];
    const float* B4v = (const float*)d_in[8];
    float* out = (float*)d_out;

    dim3 pgrid(NPOP, NSLICE);
    precompute_kernel<<<pgrid, 256>>>(L1, L2, L3, L4, B1, B2, B3, B4v);

    cudaLaunchConfig_t cfg = {};
    cfg.gridDim  = dim3(BPP, NPOP);
    cfg.blockDim = dim3(TPB);
    cfg.dynamicSmemBytes = 0;
    cfg.stream = 0;
    cudaLaunchAttribute attrs[1];
    attrs[0].id = cudaLaunchAttributeProgrammaticStreamSerialization;
    attrs[0].val.programmaticStreamSerializationAllowed = 1;
    cfg.attrs = attrs;
    cfg.numAttrs = 1;
    cudaLaunchKernelEx(&cfg, eval_kernel, X, out);
}